// round 13
// baseline (speedup 1.0000x reference)
#include <cuda_runtime.h>
#include <math.h>

// Problem constants
#define BB    8
#define AA    512
#define NBH   64
#define FD    128
#define GD    50
// padded shared strides
#define NSTR  132   // s_nbh row stride
#define USTR  136   // u row stride
#define FSTR  52    // s_fij row stride
#define WSTR  404   // s_wf f-block stride (16B-aligned; lf*20 mod 32 distinct for 4-lane groups)
// s_un float offsets
#define U_A0   0        // u atom0 [0,1088)  (also P1 partials [0,1024) before P5 a=0)
#define U_A1   1088     // u atom1 [1088,2176)
#define FIJ_O  1088     // fij current atom [1088,4416)
#define RED_O  1088     // P3 red (u64 view) [1088,3200)
#define P6P_O  2176     // P6/P7 partials [2176,3200) (u64[512])
#define MSG_O  3200     // msg [3200,3456)

typedef unsigned long long u64;

__device__ __forceinline__ void fma2(u64 &d, u64 a, u64 b) {
    asm("fma.rn.f32x2 %0, %1, %2, %0;" : "+l"(d) : "l"(a), "l"(b));
}
__device__ __forceinline__ u64 pk2(float lo, float hi) {
    u64 r; asm("mov.b64 %0, {%1, %2};" : "=l"(r) : "f"(lo), "f"(hi)); return r;
}
__device__ __forceinline__ float2 upk2(u64 v) {
    float2 t; asm("mov.b64 {%0, %1}, %2;" : "=f"(t.x), "=f"(t.y) : "l"(v)); return t;
}
__device__ __forceinline__ u64 mul2_(u64 a, u64 b) {
    u64 r; asm("mul.rn.f32x2 %0, %1, %2;" : "=l"(r) : "l"(a), "l"(b)); return r;
}
__device__ __forceinline__ u64 add2_(u64 a, u64 b) {
    u64 r; asm("add.rn.f32x2 %0, %1, %2;" : "=l"(r) : "l"(a), "l"(b)); return r;
}

__device__ int g_mask_u8;

// Detect 1-byte bool vs 4-byte int mask (deterministic).
__global__ void detect_mask_kernel(const unsigned char* __restrict__ m) {
    __shared__ int found;
    if (threadIdx.x == 0) found = 0;
    __syncthreads();
    int acc = 0;
    for (int i = threadIdx.x * 4 + 1; i < 8192; i += blockDim.x * 4)
        if (m[i]) acc = 1;
    if (acc) atomicOr(&found, 1);
    __syncthreads();
    if (threadIdx.x == 0) g_mask_u8 = found;
}

__global__ __launch_bounds__(256, 3)
void tdt_kernel(const float* __restrict__ x,
                const float* __restrict__ r_ij,
                const float* __restrict__ f_ij,
                const float* __restrict__ Wf,
                const float* __restrict__ bfilt,
                const float* __restrict__ Wq,
                const float* __restrict__ Wk,
                const float* __restrict__ Wv,
                const float* __restrict__ Wo,
                const float* __restrict__ bo,
                const int*   __restrict__ nbr,
                const void*  __restrict__ maskp,
                float*       __restrict__ out)
{
    __shared__ __align__(16) float s_nbh[NBH * NSTR];   // 33.8 KB (epoch: s_wf)
    __shared__ __align__(16) float s_pt[2112];          // p^T per atom a*1056; sc/scT overlay
    __shared__ __align__(16) float s_un[4416];          // u / fij / red / partials / msg
    __shared__ __align__(16) float s_q[2 * FD];
    __shared__ __align__(16) float s_xa[2 * FD];
    __shared__ float s_C[2 * NBH];
    __shared__ int   s_nb[2 * NBH];
    __shared__ int   s_mk[2 * NBH];

    float* const s_wf = s_nbh;

    const int tid   = threadIdx.x;
    const int atom0 = blockIdx.x * 2;                  // pair never crosses batch (512 even)
    const int b     = atom0 >> 9;
    const float* xb = x + (size_t)b * (AA * FD);
    const size_t an = (size_t)atom0 * NBH;             // 128 n-slots for the pair
    const int u8 = g_mask_u8;

    // ---- P0: stage Wf (float4), fij_a0, x pair ----
    {
        const float4* wsrc = (const float4*)Wf;        // 1600 float4
        for (int i = tid; i < 1600; i += 256) {
            int g = i >> 5, rem = i & 31;              // rem = ftb*2 + k4
            int ftb = rem >> 1, k4 = rem & 1;
            *(float4*)(s_wf + ftb * WSTR + g * 8 + k4 * 4) = wsrc[i];
        }
    }
    {
        const float2* fsrc = (const float2*)(f_ij + an * GD);
        for (int i = tid; i < 1600; i += 256) {
            int r = i / 25, c2 = i - r * 25;
            *(float2*)(s_un + FIJ_O + r * FSTR + c2 * 2) = fsrc[i];
        }
    }
    s_xa[tid] = x[(size_t)atom0 * FD + tid];
    if (tid < 128) {
        float r = r_ij[an + tid];
        s_C[tid]  = (r < 5.0f) ? 0.5f * (cospif(r * 0.2f) + 1.0f) : 0.0f;
        s_nb[tid] = nbr[an + tid];
        int mv;
        if (u8) mv = ((const unsigned char*)maskp)[an + tid];
        else    mv = ((const int*)maskp)[an + tid];
        s_mk[tid] = (mv != 0);
    }
    __syncthreads();

    // ---- P1: q = x @ Wq, BOTH atoms; u64 c-pair loads, 4-way k-split ----
    {
        const int cg = tid & 63, q = tid >> 6;         // c = 2*cg, j in [q*32, q*32+32)
        const float* wq  = Wq + (size_t)(q * 32) * FD + 2 * cg;
        const float* xj0 = s_xa + q * 32;
        const float* xj1 = s_xa + 128 + q * 32;
        u64 a0 = 0ull, a1 = 0ull;
        #pragma unroll 8
        for (int j = 0; j < 32; ++j) {
            u64 w = *(const u64*)(wq + j * FD);
            float v0 = xj0[j], v1 = xj1[j];
            fma2(a0, pk2(v0, v0), w);
            fma2(a1, pk2(v1, v1), w);
        }
        u64* part = (u64*)(s_un + U_A0);
        part[q * 64 + cg]       = a0;
        part[256 + q * 64 + cg] = a1;
    }
    __syncthreads();
    if (tid < 128) {
        const int a = tid >> 6, cg = tid & 63;
        const u64* part = (const u64*)(s_un + U_A0) + a * 256;
        u64 s = add2_(add2_(part[cg], part[64 + cg]),
                      add2_(part[128 + cg], part[192 + cg]));
        *(u64*)(s_q + a * 128 + 2 * cg) = s;
    }
    __syncthreads();

    // ---- P2a: p^T[j][h] for BOTH atoms, one Wk pass (coalesced rows) ----
    {
        const int w = tid >> 5, k = tid & 31, h = k >> 2;
        const float4 qc0 = *(const float4*)(s_q + 4 * k);
        const float4 qc1 = *(const float4*)(s_q + 128 + 4 * k);
        #pragma unroll 4
        for (int jj = 0; jj < 16; ++jj) {
            const int j = w * 16 + jj;
            float4 wv = *(const float4*)(Wk + j * FD + 4 * k);
            float d0 = wv.x * qc0.x + wv.y * qc0.y + wv.z * qc0.z + wv.w * qc0.w;
            float d1 = wv.x * qc1.x + wv.y * qc1.y + wv.z * qc1.z + wv.w * qc1.w;
            d0 += __shfl_xor_sync(0xffffffffu, d0, 1);
            d0 += __shfl_xor_sync(0xffffffffu, d0, 2);
            d1 += __shfl_xor_sync(0xffffffffu, d1, 1);
            d1 += __shfl_xor_sync(0xffffffffu, d1, 2);
            if ((k & 3) == 0) {
                s_pt[j * 8 + h]        = d0;
                s_pt[1056 + j * 8 + h] = d1;
            }
        }
    }

    // ================= per-atom loop =================
    for (int a = 0; a < 2; ++a) {
        if (a == 1) {
            // s_nbh free after P5_a0 sync: restage Wf + fij_a1
            const float4* wsrc = (const float4*)Wf;
            for (int i = tid; i < 1600; i += 256) {
                int g = i >> 5, rem = i & 31;
                int ftb = rem >> 1, k4 = rem & 1;
                *(float4*)(s_wf + ftb * WSTR + g * 8 + k4 * 4) = wsrc[i];
            }
            const float2* fsrc = (const float2*)(f_ij + (an + NBH) * GD);
            for (int i = tid; i < 1600; i += 256) {
                int r = i / 25, c2 = i - r * 25;
                *(float2*)(s_un + FIJ_O + r * FSTR + c2 * 2) = fsrc[i];
            }
            __syncthreads();
        }

        // ---- P2b: filter GEMM + cutoff + gather -> s_nbh
        //      2x4 warp-tiling: warp covers n[wn*32,+32) x f[wf*32,+32);
        //      unique w-bytes/warp 25.6KB -> 6.4KB. Thread tile unchanged 4n x 8f. ----
        {
            const int wrp = tid >> 5, lane = tid & 31;
            const int wf = wrp & 3, wn = wrp >> 2;     // 4 f-slices x 2 n-halves
            const int lf = lane & 3, ln = lane >> 2;   // 4 f-blocks x 8 n-groups
            const int ft = wf * 4 + lf, nt = wn * 8 + ln;
            const int f0 = ft * 8, n0 = nt * 4;
            u64 acc[4][4];
            {
                ulonglong2 bA = *(const ulonglong2*)(bfilt + f0);
                ulonglong2 bB = *(const ulonglong2*)(bfilt + f0 + 4);
                #pragma unroll
                for (int i = 0; i < 4; ++i) {
                    acc[i][0] = bA.x; acc[i][1] = bA.y;
                    acc[i][2] = bB.x; acc[i][3] = bB.y;
                }
            }
            const float* fr = s_un + FIJ_O + n0 * FSTR;
            const float* wbase = s_wf + ft * WSTR;
            #pragma unroll 2
            for (int g = 0; g < 48; g += 4) {
                float4 a4[4];
                #pragma unroll
                for (int i = 0; i < 4; ++i)
                    a4[i] = *(const float4*)(fr + i * FSTR + g);
                #pragma unroll
                for (int s = 0; s < 4; ++s) {
                    const ulonglong2* wr = (const ulonglong2*)(wbase + (g + s) * 8);
                    ulonglong2 wA = wr[0], wB = wr[1];
                    #pragma unroll
                    for (int i = 0; i < 4; ++i) {
                        float av = (s == 0) ? a4[i].x : (s == 1) ? a4[i].y :
                                   (s == 2) ? a4[i].z : a4[i].w;
                        u64 a2 = pk2(av, av);
                        fma2(acc[i][0], a2, wA.x);
                        fma2(acc[i][1], a2, wA.y);
                        fma2(acc[i][2], a2, wB.x);
                        fma2(acc[i][3], a2, wB.y);
                    }
                }
            }
            {   // remainder g = 48, 49
                float2 ar[4];
                #pragma unroll
                for (int i = 0; i < 4; ++i)
                    ar[i] = *(const float2*)(fr + i * FSTR + 48);
                #pragma unroll
                for (int s = 0; s < 2; ++s) {
                    const ulonglong2* wr = (const ulonglong2*)(wbase + (48 + s) * 8);
                    ulonglong2 wA = wr[0], wB = wr[1];
                    #pragma unroll
                    for (int i = 0; i < 4; ++i) {
                        float av = s ? ar[i].y : ar[i].x;
                        u64 a2 = pk2(av, av);
                        fma2(acc[i][0], a2, wA.x);
                        fma2(acc[i][1], a2, wA.y);
                        fma2(acc[i][2], a2, wB.x);
                        fma2(acc[i][3], a2, wB.y);
                    }
                }
            }
            __syncthreads();   // all s_wf reads done before s_nbh stores (alias)
            #pragma unroll
            for (int i = 0; i < 4; ++i) {
                const int n = n0 + i;
                const float c = s_C[a * NBH + n];
                const u64 c2 = pk2(c, c);
                const float* xg = xb + (size_t)s_nb[a * NBH + n] * FD + f0;
                ulonglong2 gA = *(const ulonglong2*)(xg);
                ulonglong2 gB = *(const ulonglong2*)(xg + 4);
                ulonglong2 rA, rB;
                rA.x = mul2_(mul2_(acc[i][0], gA.x), c2);
                rA.y = mul2_(mul2_(acc[i][1], gA.y), c2);
                rB.x = mul2_(mul2_(acc[i][2], gB.x), c2);
                rB.y = mul2_(mul2_(acc[i][3], gB.y), c2);
                *(ulonglong2*)(s_nbh + n * NSTR + f0)     = rA;
                *(ulonglong2*)(s_nbh + n * NSTR + f0 + 4) = rB;
            }
        }
        __syncthreads();

        // ---- P3: score partials, tile read once ----
        {
            const int n = tid & 63, jh = tid >> 6;
            const float* row = s_nbh + n * NSTR + jh * 32;
            const float* pt  = s_pt + a * 1056 + (jh * 32) * 8;
            u64 acc[4] = {0ull, 0ull, 0ull, 0ull};
            #pragma unroll 4
            for (int j = 0; j < 32; j += 4) {
                float4 v = *(const float4*)(row + j);
                #pragma unroll
                for (int s = 0; s < 4; ++s) {
                    float vv = (s == 0) ? v.x : (s == 1) ? v.y : (s == 2) ? v.z : v.w;
                    u64 v2 = pk2(vv, vv);
                    const ulonglong2* pp = (const ulonglong2*)(pt + (j + s) * 8);
                    ulonglong2 p0 = pp[0], p1 = pp[1];
                    fma2(acc[0], v2, p0.x);
                    fma2(acc[1], v2, p0.y);
                    fma2(acc[2], v2, p1.x);
                    fma2(acc[3], v2, p1.y);
                }
            }
            u64* red = (u64*)(s_un + RED_O);
            #pragma unroll
            for (int t = 0; t < 4; ++t)
                red[(jh * 4 + t) * 66 + n] = acc[t];
        }
        __syncthreads();

        // ---- P3r: combine quarters, mask, scale -> sc[h][n] (overlay p_a) ----
        {
            const int n = tid >> 2, hp = tid & 3;
            const u64* red = (const u64*)(s_un + RED_O);
            u64 s0 = add2_(red[(0 * 4 + hp) * 66 + n], red[(1 * 4 + hp) * 66 + n]);
            u64 s1 = add2_(red[(2 * 4 + hp) * 66 + n], red[(3 * 4 + hp) * 66 + n]);
            float2 p = upk2(add2_(s0, s1));
            const bool m = (s_mk[a * NBH + n] != 0);
            float* sc = s_pt + a * 1056;
            sc[(2 * hp) * 64 + n]     = m ? p.x * 0.25f : -1e9f;
            sc[(2 * hp + 1) * 64 + n] = m ? p.y * 0.25f : -1e9f;
        }
        __syncthreads();

        // ---- P4: softmax, one warp per head; attn transposed [n][h] ----
        {
            const int h = tid >> 5, lane = tid & 31;
            const float* sc = s_pt + a * 1056 + h * 64;
            float* scT = s_pt + a * 1056 + 512;
            float v0 = sc[lane], v1 = sc[lane + 32];
            float mx = fmaxf(v0, v1);
            #pragma unroll
            for (int o = 16; o > 0; o >>= 1)
                mx = fmaxf(mx, __shfl_xor_sync(0xffffffffu, mx, o));
            float e0 = __expf(v0 - mx), e1 = __expf(v1 - mx);
            float s = e0 + e1;
            #pragma unroll
            for (int o = 16; o > 0; o >>= 1)
                s += __shfl_xor_sync(0xffffffffu, s, o);
            float inv = 1.0f / s;
            scT[lane * 8 + h]        = e0 * inv;
            scT[(lane + 32) * 8 + h] = e1 * inv;
        }
        __syncthreads();

        // ---- P5: u[h][j], column-owned, tile read once ----
        {
            const int w = tid >> 5, lane = tid & 31;
            const int half = lane >> 4, cc = lane & 15;
            const int col = w * 16 + cc;
            const int nbase = half * 32;
            const float* scT = s_pt + a * 1056 + 512;
            float* su = s_un + a * 1088;
            u64 acc[4] = {0ull, 0ull, 0ull, 0ull};
            #pragma unroll 4
            for (int i = 0; i < 32; ++i) {
                const int n = nbase + i;
                float v = s_nbh[n * NSTR + col];
                u64 v2 = pk2(v, v);
                ulonglong2 a0 = *(const ulonglong2*)(scT + n * 8);
                ulonglong2 a1 = *(const ulonglong2*)(scT + n * 8 + 4);
                fma2(acc[0], v2, a0.x);
                fma2(acc[1], v2, a0.y);
                fma2(acc[2], v2, a1.x);
                fma2(acc[3], v2, a1.y);
            }
            #pragma unroll
            for (int t = 0; t < 4; ++t) {
                float2 p = upk2(acc[t]);
                p.x += __shfl_xor_sync(0xffffffffu, p.x, 16);
                p.y += __shfl_xor_sync(0xffffffffu, p.y, 16);
                if (half == 0) {
                    su[(2 * t) * USTR + col]     = p.x;
                    su[(2 * t + 1) * USTR + col] = p.y;
                }
            }
        }
        __syncthreads();
    }

    // ---- P6: msg for BOTH atoms, one Wv pass (u64 c-pair, 4-way k-split) ----
    {
        const int cg = tid & 63, q = tid >> 6;
        const int h = cg >> 3;                        // c = 2cg -> h = c/16
        const float* wv = Wv + (size_t)(q * 32) * FD + 2 * cg;
        const float* u0 = s_un + U_A0 + h * USTR + q * 32;
        const float* u1 = s_un + U_A1 + h * USTR + q * 32;
        u64 a0 = 0ull, a1 = 0ull;
        #pragma unroll 8
        for (int j = 0; j < 32; ++j) {
            u64 w = *(const u64*)(wv + j * FD);
            float v0 = u0[j], v1 = u1[j];
            fma2(a0, pk2(v0, v0), w);
            fma2(a1, pk2(v1, v1), w);
        }
        u64* part = (u64*)(s_un + P6P_O);
        part[q * 64 + cg]       = a0;
        part[256 + q * 64 + cg] = a1;
    }
    __syncthreads();
    if (tid < 128) {
        const int a = tid >> 6, cg = tid & 63;
        const u64* part = (const u64*)(s_un + P6P_O) + a * 256;
        u64 s = add2_(add2_(part[cg], part[64 + cg]),
                      add2_(part[128 + cg], part[192 + cg]));
        *(u64*)(s_un + MSG_O + a * 128 + 2 * cg) = s;
    }
    __syncthreads();

    // ---- P7: out for BOTH atoms, one Wo pass ----
    {
        const int cg = tid & 63, q = tid >> 6;
        const float* wo = Wo + (size_t)(q * 32) * FD + 2 * cg;
        const float* m0 = s_un + MSG_O + q * 32;
        const float* m1 = s_un + MSG_O + 128 + q * 32;
        u64 a0 = 0ull, a1 = 0ull;
        #pragma unroll 8
        for (int j = 0; j < 32; ++j) {
            u64 w = *(const u64*)(wo + j * FD);
            float v0 = m0[j], v1 = m1[j];
            fma2(a0, pk2(v0, v0), w);
            fma2(a1, pk2(v1, v1), w);
        }
        u64* part = (u64*)(s_un + P6P_O);   // P6 partials dead (reduce barrier passed)
        part[q * 64 + cg]       = a0;
        part[256 + q * 64 + cg] = a1;
    }
    __syncthreads();
    if (tid < 128) {
        const int a = tid >> 6, cg = tid & 63;
        const u64* part = (const u64*)(s_un + P6P_O) + a * 256;
        u64 s = add2_(add2_(part[cg], part[64 + cg]),
                      add2_(part[128 + cg], part[192 + cg]));
        u64 bo2 = *(const u64*)(bo + 2 * cg);
        u64 xa2 = *(const u64*)(s_xa + a * 128 + 2 * cg);
        u64 r = add2_(add2_(s, bo2), xa2);
        *(u64*)(out + (size_t)atom0 * FD + a * 128 + 2 * cg) = r;
    }
}

extern "C" void kernel_launch(void* const* d_in, const int* in_sizes, int n_in,
                              void* d_out, int out_size)
{
    // metadata order: e, x, t, r_ij, f_ij, W_filt, b_filt, Wq, Wk, Wv, Wo, bo,
    //                 neighbors, neighbor_mask     (e and t are unused)
    const float* x    = (const float*)d_in[1];
    const float* r    = (const float*)d_in[3];
    const float* fij  = (const float*)d_in[4];
    const float* Wf   = (const float*)d_in[5];
    const float* bf   = (const float*)d_in[6];
    const float* Wq   = (const float*)d_in[7];
    const float* Wk   = (const float*)d_in[8];
    const float* Wv   = (const float*)d_in[9];
    const float* Wo   = (const float*)d_in[10];
    const float* bo   = (const float*)d_in[11];
    const int*   nbr  = (const int*)d_in[12];
    const void*  mk   = d_in[13];

    detect_mask_kernel<<<1, 256>>>((const unsigned char*)mk);
    tdt_kernel<<<BB * AA / 2, 256>>>(x, r, fij, Wf, bf, Wq, Wk, Wv, Wo, bo,
                                     nbr, mk, (float*)d_out);
}

// round 15
// speedup vs baseline: 1.0450x; 1.0450x over previous
#include <cuda_runtime.h>
#include <math.h>

// Problem constants
#define BB    8
#define AA    512
#define NBH   64
#define FD    128
#define GD    50
// padded shared strides
#define NSTR  132   // s_nbh row stride
#define USTR  136   // u row stride
#define FSTR  52    // s_fij row stride (+8 pad per 4-row group; group stride 216)
#define WSTR  404   // s_wf f-block stride (16B-aligned; lf*20 mod 32 distinct)
// s_un float offsets
#define U_A0   0        // u atom0 [0,1088)  (also P1 partials [0,1024) before P5 a=0)
#define U_A1   1088     // u atom1 [1088,2176)
#define FIJ_O  1088     // fij current atom [1088,4544) padded layout
#define RED_O  1088     // P3 red (u64 view) [1088,3200)
#define P6P_O  2176     // P6/P7 partials [2176,3200) (u64[512])
#define MSG_O  3200     // msg [3200,3456)
#define SUN_SZ 4544

typedef unsigned long long u64;

__device__ __forceinline__ void fma2(u64 &d, u64 a, u64 b) {
    asm("fma.rn.f32x2 %0, %1, %2, %0;" : "+l"(d) : "l"(a), "l"(b));
}
__device__ __forceinline__ u64 pk2(float lo, float hi) {
    u64 r; asm("mov.b64 %0, {%1, %2};" : "=l"(r) : "f"(lo), "f"(hi)); return r;
}
__device__ __forceinline__ float2 upk2(u64 v) {
    float2 t; asm("mov.b64 {%0, %1}, %2;" : "=f"(t.x), "=f"(t.y) : "l"(v)); return t;
}
__device__ __forceinline__ u64 mul2_(u64 a, u64 b) {
    u64 r; asm("mul.rn.f32x2 %0, %1, %2;" : "=l"(r) : "l"(a), "l"(b)); return r;
}
__device__ __forceinline__ u64 add2_(u64 a, u64 b) {
    u64 r; asm("add.rn.f32x2 %0, %1, %2;" : "=l"(r) : "l"(a), "l"(b)); return r;
}

__device__ int g_mask_u8;

// Detect 1-byte bool vs 4-byte int mask (deterministic).
__global__ void detect_mask_kernel(const unsigned char* __restrict__ m) {
    __shared__ int found;
    if (threadIdx.x == 0) found = 0;
    __syncthreads();
    int acc = 0;
    for (int i = threadIdx.x * 4 + 1; i < 8192; i += blockDim.x * 4)
        if (m[i]) acc = 1;
    if (acc) atomicOr(&found, 1);
    __syncthreads();
    if (threadIdx.x == 0) g_mask_u8 = found;
}

__global__ __launch_bounds__(256, 3)
void tdt_kernel(const float* __restrict__ x,
                const float* __restrict__ r_ij,
                const float* __restrict__ f_ij,
                const float* __restrict__ Wf,
                const float* __restrict__ bfilt,
                const float* __restrict__ Wq,
                const float* __restrict__ Wk,
                const float* __restrict__ Wv,
                const float* __restrict__ Wo,
                const float* __restrict__ bo,
                const int*   __restrict__ nbr,
                const void*  __restrict__ maskp,
                float*       __restrict__ out)
{
    __shared__ __align__(16) float s_nbh[NBH * NSTR];   // 33.8 KB (epoch: s_wf)
    __shared__ __align__(16) float s_pt[2112];          // p^T per atom a*1056; sc/scT overlay
    __shared__ __align__(16) float s_un[SUN_SZ];        // u / fij / red / partials / msg
    __shared__ __align__(16) float s_q[2 * FD];
    __shared__ __align__(16) float s_xa[2 * FD];
    __shared__ float s_C[2 * NBH];
    __shared__ int   s_nb[2 * NBH];
    __shared__ int   s_mk[2 * NBH];

    float* const s_wf = s_nbh;

    const int tid   = threadIdx.x;
    const int atom0 = blockIdx.x * 2;                  // pair never crosses batch (512 even)
    const int b     = atom0 >> 9;
    const float* xb = x + (size_t)b * (AA * FD);
    const size_t an = (size_t)atom0 * NBH;             // 128 n-slots for the pair
    const int u8 = g_mask_u8;

    // ---- P0: stage Wf (float4), fij_a0 (padded per 4-row group), x pair ----
    {
        const float4* wsrc = (const float4*)Wf;        // 1600 float4
        for (int i = tid; i < 1600; i += 256) {
            int g = i >> 5, rem = i & 31;              // rem = ftb*2 + k4
            int ftb = rem >> 1, k4 = rem & 1;
            *(float4*)(s_wf + ftb * WSTR + g * 8 + k4 * 4) = wsrc[i];
        }
    }
    {
        const float2* fsrc = (const float2*)(f_ij + an * GD);
        for (int i = tid; i < 1600; i += 256) {
            int r = i / 25, c2 = i - r * 25;
            *(float2*)(s_un + FIJ_O + r * FSTR + (r >> 2) * 8 + c2 * 2) = fsrc[i];
        }
    }
    s_xa[tid] = x[(size_t)atom0 * FD + tid];
    if (tid < 128) {
        float r = r_ij[an + tid];
        s_C[tid]  = (r < 5.0f) ? 0.5f * (cospif(r * 0.2f) + 1.0f) : 0.0f;
        s_nb[tid] = nbr[an + tid];
        int mv;
        if (u8) mv = ((const unsigned char*)maskp)[an + tid];
        else    mv = ((const int*)maskp)[an + tid];
        s_mk[tid] = (mv != 0);
    }
    __syncthreads();

    // ---- P1: q = x @ Wq, BOTH atoms; u64 c-pair loads, 4-way k-split ----
    {
        const int cg = tid & 63, q = tid >> 6;         // c = 2*cg, j in [q*32, q*32+32)
        const float* wq  = Wq + (size_t)(q * 32) * FD + 2 * cg;
        const float* xj0 = s_xa + q * 32;
        const float* xj1 = s_xa + 128 + q * 32;
        u64 a0 = 0ull, a1 = 0ull;
        #pragma unroll 8
        for (int j = 0; j < 32; ++j) {
            u64 w = *(const u64*)(wq + j * FD);
            float v0 = xj0[j], v1 = xj1[j];
            fma2(a0, pk2(v0, v0), w);
            fma2(a1, pk2(v1, v1), w);
        }
        u64* part = (u64*)(s_un + U_A0);
        part[q * 64 + cg]       = a0;
        part[256 + q * 64 + cg] = a1;
    }
    __syncthreads();
    if (tid < 128) {
        const int a = tid >> 6, cg = tid & 63;
        const u64* part = (const u64*)(s_un + U_A0) + a * 256;
        u64 s = add2_(add2_(part[cg], part[64 + cg]),
                      add2_(part[128 + cg], part[192 + cg]));
        *(u64*)(s_q + a * 128 + 2 * cg) = s;
    }
    __syncthreads();

    // ---- P2a: p^T[j][h] for BOTH atoms, one Wk pass (coalesced rows) ----
    {
        const int w = tid >> 5, k = tid & 31, h = k >> 2;
        const float4 qc0 = *(const float4*)(s_q + 4 * k);
        const float4 qc1 = *(const float4*)(s_q + 128 + 4 * k);
        #pragma unroll 4
        for (int jj = 0; jj < 16; ++jj) {
            const int j = w * 16 + jj;
            float4 wv = *(const float4*)(Wk + j * FD + 4 * k);
            float d0 = wv.x * qc0.x + wv.y * qc0.y + wv.z * qc0.z + wv.w * qc0.w;
            float d1 = wv.x * qc1.x + wv.y * qc1.y + wv.z * qc1.z + wv.w * qc1.w;
            d0 += __shfl_xor_sync(0xffffffffu, d0, 1);
            d0 += __shfl_xor_sync(0xffffffffu, d0, 2);
            d1 += __shfl_xor_sync(0xffffffffu, d1, 1);
            d1 += __shfl_xor_sync(0xffffffffu, d1, 2);
            if ((k & 3) == 0) {
                s_pt[j * 8 + h]        = d0;
                s_pt[1056 + j * 8 + h] = d1;
            }
        }
    }

    // ================= per-atom loop =================
    for (int a = 0; a < 2; ++a) {
        if (a == 1) {
            // s_nbh free after P5_a0 sync: restage Wf + fij_a1
            const float4* wsrc = (const float4*)Wf;
            for (int i = tid; i < 1600; i += 256) {
                int g = i >> 5, rem = i & 31;
                int ftb = rem >> 1, k4 = rem & 1;
                *(float4*)(s_wf + ftb * WSTR + g * 8 + k4 * 4) = wsrc[i];
            }
            const float2* fsrc = (const float2*)(f_ij + (an + NBH) * GD);
            for (int i = tid; i < 1600; i += 256) {
                int r = i / 25, c2 = i - r * 25;
                *(float2*)(s_un + FIJ_O + r * FSTR + (r >> 2) * 8 + c2 * 2) = fsrc[i];
            }
            __syncthreads();
        }

        // ---- P2b: filter GEMM + cutoff + gather -> s_nbh
        //      warp = (wn 4 n-groups) x (wf 2 f-halves); lane = (ln 4) x (lf 8).
        //      w-load: 8 uniq addr, banks lf*20 mod 32 all distinct -> 1 wf.
        //      a-load: 4 uniq addr, group stride 216 -> banks ln*24 distinct -> 1 wf. ----
        {
            const int wrp = tid >> 5, lane = tid & 31;
            const int wf = wrp & 1, wn = wrp >> 1;
            const int lf = lane & 7, ln = lane >> 3;
            const int ft = wf * 8 + lf, nt = wn * 4 + ln;
            const int f0 = ft * 8, n0 = nt * 4;
            u64 acc[4][4];
            {
                ulonglong2 bA = *(const ulonglong2*)(bfilt + f0);
                ulonglong2 bB = *(const ulonglong2*)(bfilt + f0 + 4);
                #pragma unroll
                for (int i = 0; i < 4; ++i) {
                    acc[i][0] = bA.x; acc[i][1] = bA.y;
                    acc[i][2] = bB.x; acc[i][3] = bB.y;
                }
            }
            const float* fr = s_un + FIJ_O + nt * 216;   // 216 = 4*FSTR + 8 pad
            const float* wbase = s_wf + ft * WSTR;
            #pragma unroll 2
            for (int g = 0; g < 48; g += 4) {
                float4 a4[4];
                #pragma unroll
                for (int i = 0; i < 4; ++i)
                    a4[i] = *(const float4*)(fr + i * FSTR + g);
                #pragma unroll
                for (int s = 0; s < 4; ++s) {
                    const ulonglong2* wr = (const ulonglong2*)(wbase + (g + s) * 8);
                    ulonglong2 wA = wr[0], wB = wr[1];
                    #pragma unroll
                    for (int i = 0; i < 4; ++i) {
                        float av = (s == 0) ? a4[i].x : (s == 1) ? a4[i].y :
                                   (s == 2) ? a4[i].z : a4[i].w;
                        u64 a2 = pk2(av, av);
                        fma2(acc[i][0], a2, wA.x);
                        fma2(acc[i][1], a2, wA.y);
                        fma2(acc[i][2], a2, wB.x);
                        fma2(acc[i][3], a2, wB.y);
                    }
                }
            }
            {   // remainder g = 48, 49
                float2 ar[4];
                #pragma unroll
                for (int i = 0; i < 4; ++i)
                    ar[i] = *(const float2*)(fr + i * FSTR + 48);
                #pragma unroll
                for (int s = 0; s < 2; ++s) {
                    const ulonglong2* wr = (const ulonglong2*)(wbase + (48 + s) * 8);
                    ulonglong2 wA = wr[0], wB = wr[1];
                    #pragma unroll
                    for (int i = 0; i < 4; ++i) {
                        float av = s ? ar[i].y : ar[i].x;
                        u64 a2 = pk2(av, av);
                        fma2(acc[i][0], a2, wA.x);
                        fma2(acc[i][1], a2, wA.y);
                        fma2(acc[i][2], a2, wB.x);
                        fma2(acc[i][3], a2, wB.y);
                    }
                }
            }
            __syncthreads();   // all s_wf reads done before s_nbh stores (alias)
            #pragma unroll
            for (int i = 0; i < 4; ++i) {
                const int n = n0 + i;
                const float c = s_C[a * NBH + n];
                const u64 c2 = pk2(c, c);
                const float* xg = xb + (size_t)s_nb[a * NBH + n] * FD + f0;
                ulonglong2 gA = *(const ulonglong2*)(xg);
                ulonglong2 gB = *(const ulonglong2*)(xg + 4);
                ulonglong2 rA, rB;
                rA.x = mul2_(mul2_(acc[i][0], gA.x), c2);
                rA.y = mul2_(mul2_(acc[i][1], gA.y), c2);
                rB.x = mul2_(mul2_(acc[i][2], gB.x), c2);
                rB.y = mul2_(mul2_(acc[i][3], gB.y), c2);
                *(ulonglong2*)(s_nbh + n * NSTR + f0)     = rA;
                *(ulonglong2*)(s_nbh + n * NSTR + f0 + 4) = rB;
            }
        }
        __syncthreads();

        // ---- P3: score partials, tile read once ----
        {
            const int n = tid & 63, jh = tid >> 6;
            const float* row = s_nbh + n * NSTR + jh * 32;
            const float* pt  = s_pt + a * 1056 + (jh * 32) * 8;
            u64 acc[4] = {0ull, 0ull, 0ull, 0ull};
            #pragma unroll 4
            for (int j = 0; j < 32; j += 4) {
                float4 v = *(const float4*)(row + j);
                #pragma unroll
                for (int s = 0; s < 4; ++s) {
                    float vv = (s == 0) ? v.x : (s == 1) ? v.y : (s == 2) ? v.z : v.w;
                    u64 v2 = pk2(vv, vv);
                    const ulonglong2* pp = (const ulonglong2*)(pt + (j + s) * 8);
                    ulonglong2 p0 = pp[0], p1 = pp[1];
                    fma2(acc[0], v2, p0.x);
                    fma2(acc[1], v2, p0.y);
                    fma2(acc[2], v2, p1.x);
                    fma2(acc[3], v2, p1.y);
                }
            }
            u64* red = (u64*)(s_un + RED_O);
            #pragma unroll
            for (int t = 0; t < 4; ++t)
                red[(jh * 4 + t) * 66 + n] = acc[t];
        }
        __syncthreads();

        // ---- P3r: combine quarters, mask, scale -> sc[h][n] (overlay p_a) ----
        {
            const int n = tid >> 2, hp = tid & 3;
            const u64* red = (const u64*)(s_un + RED_O);
            u64 s0 = add2_(red[(0 * 4 + hp) * 66 + n], red[(1 * 4 + hp) * 66 + n]);
            u64 s1 = add2_(red[(2 * 4 + hp) * 66 + n], red[(3 * 4 + hp) * 66 + n]);
            float2 p = upk2(add2_(s0, s1));
            const bool m = (s_mk[a * NBH + n] != 0);
            float* sc = s_pt + a * 1056;
            sc[(2 * hp) * 64 + n]     = m ? p.x * 0.25f : -1e9f;
            sc[(2 * hp + 1) * 64 + n] = m ? p.y * 0.25f : -1e9f;
        }
        __syncthreads();

        // ---- P4: softmax, one warp per head; attn transposed [n][h] ----
        {
            const int h = tid >> 5, lane = tid & 31;
            const float* sc = s_pt + a * 1056 + h * 64;
            float* scT = s_pt + a * 1056 + 512;
            float v0 = sc[lane], v1 = sc[lane + 32];
            float mx = fmaxf(v0, v1);
            #pragma unroll
            for (int o = 16; o > 0; o >>= 1)
                mx = fmaxf(mx, __shfl_xor_sync(0xffffffffu, mx, o));
            float e0 = __expf(v0 - mx), e1 = __expf(v1 - mx);
            float s = e0 + e1;
            #pragma unroll
            for (int o = 16; o > 0; o >>= 1)
                s += __shfl_xor_sync(0xffffffffu, s, o);
            float inv = 1.0f / s;
            scT[lane * 8 + h]        = e0 * inv;
            scT[(lane + 32) * 8 + h] = e1 * inv;
        }
        __syncthreads();

        // ---- P5: u[h][j], column-owned, tile read once ----
        {
            const int w = tid >> 5, lane = tid & 31;
            const int half = lane >> 4, cc = lane & 15;
            const int col = w * 16 + cc;
            const int nbase = half * 32;
            const float* scT = s_pt + a * 1056 + 512;
            float* su = s_un + a * 1088;
            u64 acc[4] = {0ull, 0ull, 0ull, 0ull};
            #pragma unroll 4
            for (int i = 0; i < 32; ++i) {
                const int n = nbase + i;
                float v = s_nbh[n * NSTR + col];
                u64 v2 = pk2(v, v);
                ulonglong2 a0 = *(const ulonglong2*)(scT + n * 8);
                ulonglong2 a1 = *(const ulonglong2*)(scT + n * 8 + 4);
                fma2(acc[0], v2, a0.x);
                fma2(acc[1], v2, a0.y);
                fma2(acc[2], v2, a1.x);
                fma2(acc[3], v2, a1.y);
            }
            #pragma unroll
            for (int t = 0; t < 4; ++t) {
                float2 p = upk2(acc[t]);
                p.x += __shfl_xor_sync(0xffffffffu, p.x, 16);
                p.y += __shfl_xor_sync(0xffffffffu, p.y, 16);
                if (half == 0) {
                    su[(2 * t) * USTR + col]     = p.x;
                    su[(2 * t + 1) * USTR + col] = p.y;
                }
            }
        }
        __syncthreads();
    }

    // ---- P6: msg for BOTH atoms, one Wv pass (u64 c-pair, 4-way k-split) ----
    {
        const int cg = tid & 63, q = tid >> 6;
        const int h = cg >> 3;                        // c = 2cg -> h = c/16
        const float* wv = Wv + (size_t)(q * 32) * FD + 2 * cg;
        const float* u0 = s_un + U_A0 + h * USTR + q * 32;
        const float* u1 = s_un + U_A1 + h * USTR + q * 32;
        u64 a0 = 0ull, a1 = 0ull;
        #pragma unroll 8
        for (int j = 0; j < 32; ++j) {
            u64 w = *(const u64*)(wv + j * FD);
            float v0 = u0[j], v1 = u1[j];
            fma2(a0, pk2(v0, v0), w);
            fma2(a1, pk2(v1, v1), w);
        }
        u64* part = (u64*)(s_un + P6P_O);
        part[q * 64 + cg]       = a0;
        part[256 + q * 64 + cg] = a1;
    }
    __syncthreads();
    if (tid < 128) {
        const int a = tid >> 6, cg = tid & 63;
        const u64* part = (const u64*)(s_un + P6P_O) + a * 256;
        u64 s = add2_(add2_(part[cg], part[64 + cg]),
                      add2_(part[128 + cg], part[192 + cg]));
        *(u64*)(s_un + MSG_O + a * 128 + 2 * cg) = s;
    }
    __syncthreads();

    // ---- P7: out for BOTH atoms, one Wo pass ----
    {
        const int cg = tid & 63, q = tid >> 6;
        const float* wo = Wo + (size_t)(q * 32) * FD + 2 * cg;
        const float* m0 = s_un + MSG_O + q * 32;
        const float* m1 = s_un + MSG_O + 128 + q * 32;
        u64 a0 = 0ull, a1 = 0ull;
        #pragma unroll 8
        for (int j = 0; j < 32; ++j) {
            u64 w = *(const u64*)(wo + j * FD);
            float v0 = m0[j], v1 = m1[j];
            fma2(a0, pk2(v0, v0), w);
            fma2(a1, pk2(v1, v1), w);
        }
        u64* part = (u64*)(s_un + P6P_O);   // P6 partials dead (reduce barrier passed)
        part[q * 64 + cg]       = a0;
        part[256 + q * 64 + cg] = a1;
    }
    __syncthreads();
    if (tid < 128) {
        const int a = tid >> 6, cg = tid & 63;
        const u64* part = (const u64*)(s_un + P6P_O) + a * 256;
        u64 s = add2_(add2_(part[cg], part[64 + cg]),
                      add2_(part[128 + cg], part[192 + cg]));
        u64 bo2 = *(const u64*)(bo + 2 * cg);
        u64 xa2 = *(const u64*)(s_xa + a * 128 + 2 * cg);
        u64 r = add2_(add2_(s, bo2), xa2);
        *(u64*)(out + (size_t)atom0 * FD + a * 128 + 2 * cg) = r;
    }
}

extern "C" void kernel_launch(void* const* d_in, const int* in_sizes, int n_in,
                              void* d_out, int out_size)
{
    // metadata order: e, x, t, r_ij, f_ij, W_filt, b_filt, Wq, Wk, Wv, Wo, bo,
    //                 neighbors, neighbor_mask     (e and t are unused)
    const float* x    = (const float*)d_in[1];
    const float* r    = (const float*)d_in[3];
    const float* fij  = (const float*)d_in[4];
    const float* Wf   = (const float*)d_in[5];
    const float* bf   = (const float*)d_in[6];
    const float* Wq   = (const float*)d_in[7];
    const float* Wk   = (const float*)d_in[8];
    const float* Wv   = (const float*)d_in[9];
    const float* Wo   = (const float*)d_in[10];
    const float* bo   = (const float*)d_in[11];
    const int*   nbr  = (const int*)d_in[12];
    const void*  mk   = d_in[13];

    detect_mask_kernel<<<1, 256>>>((const unsigned char*)mk);
    tdt_kernel<<<BB * AA / 2, 256>>>(x, r, fij, Wf, bf, Wq, Wk, Wv, Wo, bo,
                                     nbr, mk, (float*)d_out);
}